// round 2
// baseline (speedup 1.0000x reference)
#include <cuda_runtime.h>

#define N_NODES 4096
#define F_DIM   256
#define B_DIM   8

// Scratch (no cudaMalloc allowed) — __device__ globals.
__device__ float g_HW[(size_t)B_DIM * N_NODES * F_DIM];   // 33.5 MB: H @ W
__device__ float g_An[(size_t)N_NODES * N_NODES];         // 67 MB: relu(sym(A))
__device__ float g_dinv[N_NODES];                         // D^{-1/2}

// ---------------------------------------------------------------------------
// Kernel 1: HW = H(32768 x 256) @ W(256 x 256)  -> g_HW
// 128x128 tile, K-tile 8, 256 threads, 8x8 per thread.
// ---------------------------------------------------------------------------
__global__ __launch_bounds__(256) void hw_gemm(const float* __restrict__ H,
                                               const float* __restrict__ W) {
    __shared__ float As[8][128];
    __shared__ float Bs[8][128];
    int tid = threadIdx.x;
    int tx = tid & 15, ty = tid >> 4;
    int col0 = blockIdx.x * 128;
    int row0 = blockIdx.y * 128;

    float acc[8][8];
#pragma unroll
    for (int i = 0; i < 8; i++)
#pragma unroll
        for (int j = 0; j < 8; j++) acc[i][j] = 0.f;

    int ar = tid >> 1, ac = (tid & 1) * 4;   // A tile: 128 rows x 8 cols
    int br = tid >> 5, bc = (tid & 31) * 4;  // B tile: 8 rows x 128 cols

    for (int k0 = 0; k0 < F_DIM; k0 += 8) {
        float4 av = *(const float4*)(H + (size_t)(row0 + ar) * F_DIM + k0 + ac);
        As[ac + 0][ar] = av.x; As[ac + 1][ar] = av.y;
        As[ac + 2][ar] = av.z; As[ac + 3][ar] = av.w;
        float4 bv = *(const float4*)(W + (size_t)(k0 + br) * F_DIM + col0 + bc);
        *(float4*)&Bs[br][bc] = bv;
        __syncthreads();
#pragma unroll
        for (int kk = 0; kk < 8; kk++) {
            float a[8], b[8];
            float4 a0 = *(const float4*)&As[kk][ty * 8];
            float4 a1 = *(const float4*)&As[kk][ty * 8 + 4];
            float4 b0 = *(const float4*)&Bs[kk][tx * 8];
            float4 b1 = *(const float4*)&Bs[kk][tx * 8 + 4];
            a[0]=a0.x; a[1]=a0.y; a[2]=a0.z; a[3]=a0.w;
            a[4]=a1.x; a[5]=a1.y; a[6]=a1.z; a[7]=a1.w;
            b[0]=b0.x; b[1]=b0.y; b[2]=b0.z; b[3]=b0.w;
            b[4]=b1.x; b[5]=b1.y; b[6]=b1.z; b[7]=b1.w;
#pragma unroll
            for (int i = 0; i < 8; i++)
#pragma unroll
                for (int j = 0; j < 8; j++) acc[i][j] += a[i] * b[j];
        }
        __syncthreads();
    }
#pragma unroll
    for (int i = 0; i < 8; i++) {
        size_t base = (size_t)(row0 + ty * 8 + i) * F_DIM + col0 + tx * 8;
        float4 r0, r1;
        r0.x = acc[i][0]; r0.y = acc[i][1]; r0.z = acc[i][2]; r0.w = acc[i][3];
        r1.x = acc[i][4]; r1.y = acc[i][5]; r1.z = acc[i][6]; r1.w = acc[i][7];
        *(float4*)(g_HW + base) = r0;
        *(float4*)(g_HW + base + 4) = r1;
    }
}

// ---------------------------------------------------------------------------
// Kernel 2: g_An[i][j] = relu(0.5*(A[i][j] + A[j][i]))  (shared-mem transpose)
// ---------------------------------------------------------------------------
__global__ void anorm_kernel(const float* __restrict__ A) {
    __shared__ float tile[32][33];
    int j0 = blockIdx.x * 32;
    int i0 = blockIdx.y * 32;
    int tx = threadIdx.x, ty = threadIdx.y;  // 32 x 8
    // load the transposed-source block: A[j0..j0+31][i0..i0+31]
    for (int r = ty; r < 32; r += 8)
        tile[r][tx] = A[(size_t)(j0 + r) * N_NODES + i0 + tx];
    __syncthreads();
    for (int r = ty; r < 32; r += 8) {
        size_t idx = (size_t)(i0 + r) * N_NODES + (j0 + tx);
        float v = 0.5f * (A[idx] + tile[tx][r]);  // A[i][j] + A[j][i]
        g_An[idx] = v > 0.f ? v : 0.f;
    }
}

// ---------------------------------------------------------------------------
// Kernel 3: D[i] = rowsum(g_An);  g_dinv[i] = D>0 ? rsqrt(D) : 0
// ---------------------------------------------------------------------------
__global__ void rowsum_kernel() {
    int i = blockIdx.x;
    const float* row = g_An + (size_t)i * N_NODES;
    float s = 0.f;
    for (int j = threadIdx.x; j < N_NODES; j += 256) s += row[j];
    __shared__ float red[256];
    red[threadIdx.x] = s;
    __syncthreads();
    for (int off = 128; off > 0; off >>= 1) {
        if (threadIdx.x < off) red[threadIdx.x] += red[threadIdx.x + off];
        __syncthreads();
    }
    if (threadIdx.x == 0) {
        float D = red[0];
        g_dinv[i] = (D > 0.f) ? rsqrtf(D) : 0.f;
    }
}

// ---------------------------------------------------------------------------
// Kernel 4: out[b,n,o] = relu( HW[b,n,o] - d[n] * sum_m An[n,m]*d[m]*HW[b,m,o] )
// Columns c = b*256 + o folded: [4096 x 4096] @ [4096 x 2048].
// Col-tiles of 128 never straddle a batch (256 cols per batch).
// ---------------------------------------------------------------------------
__global__ __launch_bounds__(256) void main_gemm(float* __restrict__ out) {
    __shared__ float As[8][128];
    __shared__ float Bs[8][128];
    int tid = threadIdx.x;
    int tx = tid & 15, ty = tid >> 4;
    int c0 = blockIdx.x * 128;
    int n0 = blockIdx.y * 128;
    int b  = c0 >> 8;
    int o0 = c0 & 255;
    const float* HWb = g_HW + (size_t)b * N_NODES * F_DIM;

    float acc[8][8];
#pragma unroll
    for (int i = 0; i < 8; i++)
#pragma unroll
        for (int j = 0; j < 8; j++) acc[i][j] = 0.f;

    int ar = tid >> 1, ac = (tid & 1) * 4;   // A tile 128x8
    int br = tid >> 5, bc = (tid & 31) * 4;  // B tile 8x128

    for (int k0 = 0; k0 < N_NODES; k0 += 8) {
        float4 av = *(const float4*)(g_An + (size_t)(n0 + ar) * N_NODES + k0 + ac);
        As[ac + 0][ar] = av.x; As[ac + 1][ar] = av.y;
        As[ac + 2][ar] = av.z; As[ac + 3][ar] = av.w;
        float dm = g_dinv[k0 + br];
        float4 bv = *(const float4*)(HWb + (size_t)(k0 + br) * F_DIM + o0 + bc);
        bv.x *= dm; bv.y *= dm; bv.z *= dm; bv.w *= dm;
        *(float4*)&Bs[br][bc] = bv;
        __syncthreads();
#pragma unroll
        for (int kk = 0; kk < 8; kk++) {
            float a[8], bb[8];
            float4 a0 = *(const float4*)&As[kk][ty * 8];
            float4 a1 = *(const float4*)&As[kk][ty * 8 + 4];
            float4 b0 = *(const float4*)&Bs[kk][tx * 8];
            float4 b1 = *(const float4*)&Bs[kk][tx * 8 + 4];
            a[0]=a0.x; a[1]=a0.y; a[2]=a0.z; a[3]=a0.w;
            a[4]=a1.x; a[5]=a1.y; a[6]=a1.z; a[7]=a1.w;
            bb[0]=b0.x; bb[1]=b0.y; bb[2]=b0.z; bb[3]=b0.w;
            bb[4]=b1.x; bb[5]=b1.y; bb[6]=b1.z; bb[7]=b1.w;
#pragma unroll
            for (int i = 0; i < 8; i++)
#pragma unroll
                for (int j = 0; j < 8; j++) acc[i][j] += a[i] * bb[j];
        }
        __syncthreads();
    }

    float* outb = out + (size_t)b * N_NODES * F_DIM;
#pragma unroll
    for (int i = 0; i < 8; i++) {
        int n = n0 + ty * 8 + i;
        float dn = g_dinv[n];
        size_t base = (size_t)n * F_DIM + o0 + tx * 8;
        float4 h0 = *(const float4*)(HWb + base);
        float4 h1 = *(const float4*)(HWb + base + 4);
        float4 r0, r1;
        r0.x = fmaxf(h0.x - dn * acc[i][0], 0.f);
        r0.y = fmaxf(h0.y - dn * acc[i][1], 0.f);
        r0.z = fmaxf(h0.z - dn * acc[i][2], 0.f);
        r0.w = fmaxf(h0.w - dn * acc[i][3], 0.f);
        r1.x = fmaxf(h1.x - dn * acc[i][4], 0.f);
        r1.y = fmaxf(h1.y - dn * acc[i][5], 0.f);
        r1.z = fmaxf(h1.z - dn * acc[i][6], 0.f);
        r1.w = fmaxf(h1.w - dn * acc[i][7], 0.f);
        *(float4*)(outb + base) = r0;
        *(float4*)(outb + base + 4) = r1;
    }
}

// ---------------------------------------------------------------------------
extern "C" void kernel_launch(void* const* d_in, const int* in_sizes, int n_in,
                              void* d_out, int out_size) {
    const float* H = (const float*)d_in[0];  // [8, 4096, 256]
    const float* W = (const float*)d_in[1];  // [256, 256]
    const float* A = (const float*)d_in[2];  // [4096, 4096]
    float* out = (float*)d_out;              // [8, 4096, 256]

    hw_gemm<<<dim3(F_DIM / 128, (B_DIM * N_NODES) / 128), 256>>>(H, W);
    anorm_kernel<<<dim3(N_NODES / 32, N_NODES / 32), dim3(32, 8)>>>(A);
    rowsum_kernel<<<N_NODES, 256>>>();
    main_gemm<<<dim3((B_DIM * F_DIM) / 128, N_NODES / 128), 256>>>(out);
}

// round 5
// speedup vs baseline: 4.6902x; 4.6902x over previous
#include <cuda_runtime.h>
#include <cuda_bf16.h>
#include <cstdint>

#define NN 4096
#define FD 256
#define BB 8

// ---------------- scratch (__device__ globals; no allocs allowed) ----------
__device__ __nv_bfloat16 g_An[(size_t)NN * NN];          // 32MB relu(sym(A)) bf16
__device__ __nv_bfloat16 g_Bt[(size_t)BB * FD * NN];     // 16MB (d_m*HW)^T rows c=b*256+o
__device__ __nv_bfloat16 g_Hhi[(size_t)BB * NN * FD];    // 16MB H hi split
__device__ __nv_bfloat16 g_Hlo[(size_t)BB * NN * FD];    // 16MB H lo split
__device__ __nv_bfloat16 g_Wht[FD * FD];                 // W^T hi  [o][k]
__device__ __nv_bfloat16 g_Wlt[FD * FD];                 // W^T lo  [o][k]
__device__ float g_HW[(size_t)BB * NN * FD];             // 32MB H@W fp32
__device__ float g_dinv[NN];

// ---------------- PTX helpers (sm_80-era only: cp.async/ldmatrix/mma) ------
__device__ __forceinline__ uint32_t s2u(const void* p) {
    uint32_t a;
    asm("{ .reg .u64 t; cvta.to.shared.u64 t, %1; cvt.u32.u64 %0, t; }" : "=r"(a) : "l"(p));
    return a;
}

#define CPA16(dst, src) \
    asm volatile("cp.async.cg.shared.global [%0], [%1], 16;\n" :: "r"(dst), "l"(src))
#define CPA_COMMIT() asm volatile("cp.async.commit_group;\n" ::: "memory")
#define CPA_WAIT0()  asm volatile("cp.async.wait_group 0;\n" ::: "memory")
#define CPA_WAIT1()  asm volatile("cp.async.wait_group 1;\n" ::: "memory")

__device__ __forceinline__ void ldm_x4(uint32_t (&r)[4], uint32_t addr) {
    asm volatile("ldmatrix.sync.aligned.m8n8.x4.shared.b16 {%0,%1,%2,%3}, [%4];"
                 : "=r"(r[0]), "=r"(r[1]), "=r"(r[2]), "=r"(r[3]) : "r"(addr));
}

__device__ __forceinline__ void mma_bf16(float (&c)[4], const uint32_t (&a)[4],
                                         uint32_t b0, uint32_t b1) {
    asm volatile(
        "mma.sync.aligned.m16n8k16.row.col.f32.bf16.bf16.f32 "
        "{%0,%1,%2,%3}, {%4,%5,%6,%7}, {%8,%9}, {%0,%1,%2,%3};"
        : "+f"(c[0]), "+f"(c[1]), "+f"(c[2]), "+f"(c[3])
        : "r"(a[0]), "r"(a[1]), "r"(a[2]), "r"(a[3]), "r"(b0), "r"(b1));
}

// smem tile row stride: 64B of data padded to 80B -> ldmatrix & cp.async conflict-free
#define TSTRIDE 80
#define TILE_SZ (128 * TSTRIDE)   // 10240 bytes per 128x32 bf16 tile

// ---------------- prep kernels ----------------------------------------------
__global__ void anorm_k(const float* __restrict__ A) {
    __shared__ float tile[32][33];
    int j0 = blockIdx.x * 32, i0 = blockIdx.y * 32;
    int tx = threadIdx.x, ty = threadIdx.y;
    for (int r = ty; r < 32; r += 8)
        tile[r][tx] = A[(size_t)(j0 + r) * NN + i0 + tx];
    __syncthreads();
    for (int r = ty; r < 32; r += 8) {
        size_t idx = (size_t)(i0 + r) * NN + (j0 + tx);
        float v = 0.5f * (A[idx] + tile[tx][r]);
        g_An[idx] = __float2bfloat16(v > 0.f ? v : 0.f);
    }
}

__global__ void rowsum_k() {
    int i = blockIdx.x;
    const uint4* row = (const uint4*)(g_An + (size_t)i * NN);
    float s = 0.f;
    for (int j = threadIdx.x; j < NN / 8; j += 256) {
        uint4 u = row[j];
        float2 a = __bfloat1622float2(*(const __nv_bfloat162*)&u.x);
        float2 b = __bfloat1622float2(*(const __nv_bfloat162*)&u.y);
        float2 c = __bfloat1622float2(*(const __nv_bfloat162*)&u.z);
        float2 d = __bfloat1622float2(*(const __nv_bfloat162*)&u.w);
        s += (a.x + a.y) + (b.x + b.y) + (c.x + c.y) + (d.x + d.y);
    }
    __shared__ float red[256];
    red[threadIdx.x] = s;
    __syncthreads();
    for (int off = 128; off > 0; off >>= 1) {
        if (threadIdx.x < off) red[threadIdx.x] += red[threadIdx.x + off];
        __syncthreads();
    }
    if (threadIdx.x == 0) {
        float D = red[0];
        g_dinv[i] = (D > 0.f) ? rsqrtf(D) : 0.f;
    }
}

__global__ void split_h_k(const float* __restrict__ H) {
    size_t i = ((size_t)blockIdx.x * 256 + threadIdx.x) * 4;
    float4 v = *(const float4*)(H + i);
    __nv_bfloat16 h0 = __float2bfloat16(v.x), h1 = __float2bfloat16(v.y);
    __nv_bfloat16 h2 = __float2bfloat16(v.z), h3 = __float2bfloat16(v.w);
    __nv_bfloat16 l0 = __float2bfloat16(v.x - __bfloat162float(h0));
    __nv_bfloat16 l1 = __float2bfloat16(v.y - __bfloat162float(h1));
    __nv_bfloat16 l2 = __float2bfloat16(v.z - __bfloat162float(h2));
    __nv_bfloat16 l3 = __float2bfloat16(v.w - __bfloat162float(h3));
    __nv_bfloat162* hi = (__nv_bfloat162*)(g_Hhi + i);
    __nv_bfloat162* lo = (__nv_bfloat162*)(g_Hlo + i);
    hi[0] = __nv_bfloat162(h0, h1); hi[1] = __nv_bfloat162(h2, h3);
    lo[0] = __nv_bfloat162(l0, l1); lo[1] = __nv_bfloat162(l2, l3);
}

__global__ void split_wt_k(const float* __restrict__ W) {
    int o = blockIdx.x, k = threadIdx.x;
    float v = W[(size_t)k * FD + o];
    __nv_bfloat16 hi = __float2bfloat16(v);
    g_Wht[o * FD + k] = hi;
    g_Wlt[o * FD + k] = __float2bfloat16(v - __bfloat162float(hi));
}

// ---------------- HW = H@W (3-pass bf16 split via mma.sync) -----------------
// C tile 128(r) x 128(o); K=256 in 8 tiles of 32; 2-stage cp.async pipeline.
// Epilogue: stage C in smem, write g_HW (fp32) + g_Bt (d_m-scaled, transposed).
static constexpr int HW_STAGE = 4 * TILE_SZ;          // Ahi,Alo,Bhi,Blo
static constexpr int SMEM_HW  = 2 * HW_STAGE;         // 81920 (>= 128*129*4 epi)

__global__ __launch_bounds__(256, 1) void hw_gemm_mma() {
    extern __shared__ char smem[];
    uint32_t sb = s2u(smem);
    int tid = threadIdx.x, lane = tid & 31, wid = tid >> 5;
    int wm = wid >> 1, wn = wid & 1;
    int o0 = blockIdx.x * 128;
    int r0 = blockIdx.y * 128;

    const char* Ahg = (const char*)g_Hhi + (size_t)r0 * (FD * 2);
    const char* Alg = (const char*)g_Hlo + (size_t)r0 * (FD * 2);
    const char* Bhg = (const char*)g_Wht + (size_t)o0 * (FD * 2);
    const char* Blg = (const char*)g_Wlt + (size_t)o0 * (FD * 2);

    auto load = [&](int kt, int s) {
        uint32_t base = sb + s * HW_STAGE;
        size_t gk = (size_t)kt * 64;
#pragma unroll
        for (int h = 0; h < 2; h++) {
            int id = tid + h * 256;
            int r = id >> 2, c = id & 3;
            uint32_t so = r * TSTRIDE + c * 16;
            size_t go = (size_t)r * (FD * 2) + gk + c * 16;
            CPA16(base + so,               Ahg + go);
            CPA16(base + TILE_SZ + so,     Alg + go);
            CPA16(base + 2 * TILE_SZ + so, Bhg + go);
            CPA16(base + 3 * TILE_SZ + so, Blg + go);
        }
        CPA_COMMIT();
    };

    float acc[2][8][4];
#pragma unroll
    for (int i = 0; i < 2; i++)
#pragma unroll
        for (int j = 0; j < 8; j++)
#pragma unroll
            for (int v = 0; v < 4; v++) acc[i][j][v] = 0.f;

    int grp = lane >> 3, lr = lane & 7;
    int arow = wm * 32 + (grp & 1) * 8 + lr;
    int brow = wn * 64 + (grp & 1) * 8 + lr;
    int koff = (grp >> 1) * 16;

    load(0, 0);
    for (int kt = 0; kt < 8; kt++) {
        int s = kt & 1;
        if (kt + 1 < 8) { load(kt + 1, (kt + 1) & 1); CPA_WAIT1(); }
        else CPA_WAIT0();
        __syncthreads();
        uint32_t ah = sb + s * HW_STAGE;
        uint32_t al = ah + TILE_SZ;
        uint32_t bh = ah + 2 * TILE_SZ;
        uint32_t bl = ah + 3 * TILE_SZ;
#pragma unroll
        for (int kk = 0; kk < 2; kk++) {
            uint32_t ahr[2][4], alr[2][4], bhr[8][2], blr[8][2];
#pragma unroll
            for (int i = 0; i < 2; i++) {
                ldm_x4(ahr[i], ah + (arow + i * 16) * TSTRIDE + koff + kk * 32);
                ldm_x4(alr[i], al + (arow + i * 16) * TSTRIDE + koff + kk * 32);
            }
#pragma unroll
            for (int f = 0; f < 4; f++) {
                uint32_t t[4];
                ldm_x4(t, bh + (brow + f * 16) * TSTRIDE + koff + kk * 32);
                bhr[2 * f][0] = t[0]; bhr[2 * f][1] = t[2];
                bhr[2 * f + 1][0] = t[1]; bhr[2 * f + 1][1] = t[3];
                ldm_x4(t, bl + (brow + f * 16) * TSTRIDE + koff + kk * 32);
                blr[2 * f][0] = t[0]; blr[2 * f][1] = t[2];
                blr[2 * f + 1][0] = t[1]; blr[2 * f + 1][1] = t[3];
            }
#pragma unroll
            for (int i = 0; i < 2; i++)
#pragma unroll
                for (int j = 0; j < 8; j++) {
                    mma_bf16(acc[i][j], ahr[i], bhr[j][0], bhr[j][1]);
                    mma_bf16(acc[i][j], ahr[i], blr[j][0], blr[j][1]);
                    mma_bf16(acc[i][j], alr[i], bhr[j][0], bhr[j][1]);
                }
        }
        __syncthreads();
    }

    // stage C in smem [128][129] fp32
    float* cs = (float*)smem;
#pragma unroll
    for (int i = 0; i < 2; i++) {
        int ra = wm * 32 + i * 16 + (lane >> 2);
#pragma unroll
        for (int j = 0; j < 8; j++) {
            int col = wn * 64 + j * 8 + (lane & 3) * 2;
            cs[ra * 129 + col]           = acc[i][j][0];
            cs[ra * 129 + col + 1]       = acc[i][j][1];
            cs[(ra + 8) * 129 + col]     = acc[i][j][2];
            cs[(ra + 8) * 129 + col + 1] = acc[i][j][3];
        }
    }
    __syncthreads();

    int b = r0 >> 12, m0 = r0 & (NN - 1);
#pragma unroll 4
    for (int q = 0; q < 64; q++) {          // g_HW rows coalesced
        int idx = tid + q * 256;
        int r = idx >> 7, o = idx & 127;
        g_HW[(size_t)(r0 + r) * FD + o0 + o] = cs[r * 129 + o];
    }
#pragma unroll 4
    for (int q = 0; q < 64; q++) {          // g_Bt transposed, d_m-scaled
        int idx = tid + q * 256;
        int o = idx >> 7, m = idx & 127;
        float v = cs[m * 129 + o] * g_dinv[m0 + m];
        g_Bt[(size_t)(b * 256 + o0 + o) * NN + m0 + m] = __float2bfloat16(v);
    }
}

// ---------------- main GEMM: C[n,c] = An @ Bt^T, fused epilogue -------------
// 128x128x32 tiles, K=4096 (128 iters), 3-stage cp.async pipeline.
static constexpr int MAIN_STAGE = 2 * TILE_SZ;        // A + B
static constexpr int SMEM_MAIN  = 3 * MAIN_STAGE;     // 61440

__global__ __launch_bounds__(256, 1) void main_gemm_mma(float* __restrict__ out) {
    extern __shared__ char smem[];
    uint32_t sb = s2u(smem);
    int tid = threadIdx.x, lane = tid & 31, wid = tid >> 5;
    int wm = wid >> 1, wn = wid & 1;
    int c0 = blockIdx.x * 128;    // global col (c = b*256 + o)
    int n0 = blockIdx.y * 128;    // row block

    const char* Ag = (const char*)g_An + (size_t)n0 * (NN * 2);
    const char* Bg = (const char*)g_Bt + (size_t)c0 * (NN * 2);

    auto load = [&](int kt, int s) {
        uint32_t base = sb + s * MAIN_STAGE;
        size_t gk = (size_t)kt * 64;
#pragma unroll
        for (int h = 0; h < 2; h++) {
            int id = tid + h * 256;
            int r = id >> 2, c = id & 3;
            uint32_t so = r * TSTRIDE + c * 16;
            size_t go = (size_t)r * (NN * 2) + gk + c * 16;
            CPA16(base + so,           Ag + go);
            CPA16(base + TILE_SZ + so, Bg + go);
        }
        CPA_COMMIT();
    };

    float acc[2][8][4];
#pragma unroll
    for (int i = 0; i < 2; i++)
#pragma unroll
        for (int j = 0; j < 8; j++)
#pragma unroll
            for (int v = 0; v < 4; v++) acc[i][j][v] = 0.f;

    int grp = lane >> 3, lr = lane & 7;
    int arow = wm * 32 + (grp & 1) * 8 + lr;
    int brow = wn * 64 + (grp & 1) * 8 + lr;
    int koff = (grp >> 1) * 16;

    load(0, 0);
    load(1, 1);
    for (int kt = 0; kt < 128; kt++) {
        int s = kt % 3;
        CPA_WAIT1();
        __syncthreads();
        if (kt + 2 < 128) load(kt + 2, (kt + 2) % 3);
        uint32_t ab = sb + s * MAIN_STAGE;
        uint32_t bb = ab + TILE_SZ;
#pragma unroll
        for (int kk = 0; kk < 2; kk++) {
            uint32_t a[2][4], bfr[8][2];
#pragma unroll
            for (int i = 0; i < 2; i++)
                ldm_x4(a[i], ab + (arow + i * 16) * TSTRIDE + koff + kk * 32);
#pragma unroll
            for (int f = 0; f < 4; f++) {
                uint32_t t[4];
                ldm_x4(t, bb + (brow + f * 16) * TSTRIDE + koff + kk * 32);
                bfr[2 * f][0] = t[0]; bfr[2 * f][1] = t[2];
                bfr[2 * f + 1][0] = t[1]; bfr[2 * f + 1][1] = t[3];
            }
#pragma unroll
            for (int i = 0; i < 2; i++)
#pragma unroll
                for (int j = 0; j < 8; j++)
                    mma_bf16(acc[i][j], a[i], bfr[j][0], bfr[j][1]);
        }
    }

    // epilogue: out = relu(HW - d_n * acc)
    int b = c0 >> 8, obase = c0 & 255;
    const float* HWb = g_HW + (size_t)b * NN * FD;
    float* outb = out + (size_t)b * NN * FD;
#pragma unroll
    for (int i = 0; i < 2; i++) {
        int na = n0 + wm * 32 + i * 16 + (lane >> 2);
        int nb = na + 8;
        float dna = g_dinv[na], dnb = g_dinv[nb];
#pragma unroll
        for (int j = 0; j < 8; j++) {
            int o = obase + wn * 64 + j * 8 + (lane & 3) * 2;
            float2 ha = *(const float2*)(HWb + (size_t)na * FD + o);
            float2 hb = *(const float2*)(HWb + (size_t)nb * FD + o);
            float2 oa, ob;
            oa.x = fmaxf(ha.x - dna * acc[i][j][0], 0.f);
            oa.y = fmaxf(ha.y - dna * acc[i][j][1], 0.f);
            ob.x = fmaxf(hb.x - dnb * acc[i][j][2], 0.f);
            ob.y = fmaxf(hb.y - dnb * acc[i][j][3], 0.f);
            *(float2*)(outb + (size_t)na * FD + o) = oa;
            *(float2*)(outb + (size_t)nb * FD + o) = ob;
        }
    }
}

// ---------------------------------------------------------------------------
extern "C" void kernel_launch(void* const* d_in, const int* in_sizes, int n_in,
                              void* d_out, int out_size) {
    const float* H = (const float*)d_in[0];  // [8, 4096, 256]
    const float* W = (const float*)d_in[1];  // [256, 256]
    const float* A = (const float*)d_in[2];  // [4096, 4096]
    float* out = (float*)d_out;              // [8, 4096, 256]

    cudaFuncSetAttribute(hw_gemm_mma, cudaFuncAttributeMaxDynamicSharedMemorySize, SMEM_HW);
    cudaFuncSetAttribute(main_gemm_mma, cudaFuncAttributeMaxDynamicSharedMemorySize, SMEM_MAIN);

    anorm_k<<<dim3(NN / 32, NN / 32), dim3(32, 8)>>>(A);
    rowsum_k<<<NN, 256>>>();
    split_h_k<<<(BB * NN * FD) / (256 * 4), 256>>>(H);
    split_wt_k<<<FD, FD>>>(W);
    hw_gemm_mma<<<dim3(FD / 128, (BB * NN) / 128), 256, SMEM_HW>>>();
    main_gemm_mma<<<dim3((BB * FD) / 128, NN / 128), 256, SMEM_MAIN>>>(out);
}